// round 1
// baseline (speedup 1.0000x reference)
#include <cuda_runtime.h>
#include <cstdint>

// Problem constants (fixed by the dataset)
#define B_SZ  8192
#define D_K   1024   // D_IN (reduction dim)
#define U_SZ  1024   // units (softmax dim)
#define E_SZ  16     // entities

constexpr int TB      = 32;            // batch rows per CTA
constexpr int THREADS = 512;
constexpr int KC      = 8;             // K-chunk
constexpr int NCHUNK  = D_K / KC;      // 128

// Shared-memory layout (float offsets)
constexpr int OUT_OFF = 0;                         // 32*1024   fp32 out accumulator
constexpr int W_OFF   = TB * U_SZ;                 // 2 * 8 * 1024 W double buffer
constexpr int X_OFF   = W_OFF + 2 * KC * U_SZ;     // 2 * 8 * 32   X double buffer (k-major, [k][row])
constexpr int RED_OFF = X_OFF + 2 * KC * TB;       // 32 * 4       per-row warp partial sums
constexpr int TP_OFF  = RED_OFF + TB * 4;          // 32 * 16      type_prob tile
constexpr int SMEM_FLOATS = TP_OFF + TB * E_SZ;    // 50304 floats
constexpr size_t SMEM_BYTES = (size_t)SMEM_FLOATS * 4;  // 201216 B (< 227 KB)

// ---------------- packed f32x2 helpers (Blackwell; ptxas never auto-emits FFMA2) ----------------
__device__ __forceinline__ void fma2(unsigned long long& d, unsigned long long a, unsigned long long b) {
    asm("fma.rn.f32x2 %0, %1, %2, %0;" : "+l"(d) : "l"(a), "l"(b));
}
__device__ __forceinline__ unsigned long long dup2(float x) {
    unsigned long long r;
    asm("mov.b64 %0, {%1, %1};" : "=l"(r) : "f"(x));
    return r;
}
__device__ __forceinline__ unsigned long long pack2(float lo, float hi) {
    unsigned long long r;
    asm("mov.b64 %0, {%1, %2};" : "=l"(r) : "f"(lo), "f"(hi));
    return r;
}
__device__ __forceinline__ void unpack2(unsigned long long v, float& lo, float& hi) {
    asm("mov.b64 {%0, %1}, %2;" : "=f"(lo), "=f"(hi) : "l"(v));
}

// ---------------- cp.async helpers ----------------
__device__ __forceinline__ void cp16(uint32_t dst, const void* src) {
    asm volatile("cp.async.cg.shared.global [%0], [%1], 16;" :: "r"(dst), "l"(src));
}
__device__ __forceinline__ void cp4(uint32_t dst, const void* src) {
    asm volatile("cp.async.ca.shared.global [%0], [%1], 4;" :: "r"(dst), "l"(src));
}
__device__ __forceinline__ void cp_commit() {
    asm volatile("cp.async.commit_group;" ::: "memory");
}
template <int N>
__device__ __forceinline__ void cp_wait() {
    asm volatile("cp.async.wait_group %0;" :: "n"(N) : "memory");
}

// Issue one (W-chunk [8 x 1024], X-chunk [8 x 32]) pair into buffer `buf`.
__device__ __forceinline__ void issue_chunk(const float* __restrict__ W_e,
                                            const float* __restrict__ Xg,
                                            int b0, int k0, int buf, int tid,
                                            uint32_t sbase) {
    // W rows k0..k0+7, all 1024 cols. 2048 16B units; 512 threads * 4 units.
    const float* gW = W_e + (size_t)k0 * U_SZ;
    uint32_t wbase = sbase + (uint32_t)(W_OFF + buf * (KC * U_SZ)) * 4u;
#pragma unroll
    for (int q = 0; q < 4; q++) {
        int u    = tid + q * THREADS;  // 16B unit id
        int krow = u >> 8;             // 256 units per 1024-float row
        int c4   = u & 255;            // 16B column unit
        cp16(wbase + (uint32_t)(krow * U_SZ + c4 * 4) * 4u,
             gW + (size_t)krow * U_SZ + c4 * 4);
    }
    // X: gather transposed into [k][row] for broadcast-friendly reads.
    if (tid < TB * KC) {               // 256 threads, 4B each
        int r = tid >> 3;
        int k = tid & 7;
        uint32_t xdst = sbase + (uint32_t)(X_OFF + buf * (KC * TB) + k * TB + r) * 4u;
        cp4(xdst, Xg + (size_t)(b0 + r) * D_K + k0 + k);
    }
    cp_commit();
}

// Compute one K-chunk: acc[8 rows][4 col-pairs] += X * W
__device__ __forceinline__ void compute_chunk(const float* __restrict__ smem,
                                              int buf, int rg8, int cg8,
                                              unsigned long long acc[8][4]) {
    const float* Ws = smem + W_OFF + buf * (KC * U_SZ);
    const float* Xs = smem + X_OFF + buf * (KC * TB);
#pragma unroll
    for (int k = 0; k < KC; k++) {
        // 8 batch-rows of x (broadcast within warp): two LDS.128
        float4 xa = *reinterpret_cast<const float4*>(Xs + k * TB + rg8);
        float4 xb = *reinterpret_cast<const float4*>(Xs + k * TB + rg8 + 4);
        unsigned long long xp[8];
        xp[0] = dup2(xa.x); xp[1] = dup2(xa.y); xp[2] = dup2(xa.z); xp[3] = dup2(xa.w);
        xp[4] = dup2(xb.x); xp[5] = dup2(xb.y); xp[6] = dup2(xb.z); xp[7] = dup2(xb.w);
        // 8 W columns as 4 f32x2 pairs: two LDS.128, conflict-free (32B lane stride)
        const float* wr = Ws + k * U_SZ + cg8;
        ulonglong2 w0 = *reinterpret_cast<const ulonglong2*>(wr);
        ulonglong2 w1 = *reinterpret_cast<const ulonglong2*>(wr + 4);
        unsigned long long wp[4] = {w0.x, w0.y, w1.x, w1.y};
#pragma unroll
        for (int i = 0; i < 8; i++) {
#pragma unroll
            for (int j = 0; j < 4; j++) fma2(acc[i][j], xp[i], wp[j]);
        }
    }
}

__global__ void __launch_bounds__(THREADS, 1)
projection_fused_kernel(const float* __restrict__ X,    // [B, D]
                        const float* __restrict__ tp,   // [B, E] (trailing 1 squeezed)
                        const float* __restrict__ W,    // [E, D, U]
                        const float* __restrict__ bias, // [E, U]
                        float* __restrict__ out) {      // [B, U]
    extern __shared__ float smem[];
    const int tid = threadIdx.x;
    const int b0  = blockIdx.x * TB;
    const int rg8 = (tid >> 7) * 8;    // first of 8 owned batch rows
    const int cg  = tid & 127;
    const int cg8 = cg * 8;            // first of 8 owned U columns
    const int lane = tid & 31;
    const int warpLocal = (tid >> 5) & 3;  // warp index within row-group
    const uint32_t sbase = (uint32_t)__cvta_generic_to_shared(smem);

    // Zero the output accumulator
    for (int i = tid * 4; i < TB * U_SZ; i += THREADS * 4)
        *reinterpret_cast<float4*>(smem + OUT_OFF + i) = make_float4(0.f, 0.f, 0.f, 0.f);
    // Stage type_prob tile: tpS[row][e]
    if (tid < TB * E_SZ)
        smem[TP_OFF + tid] = tp[(size_t)b0 * E_SZ + tid];

    for (int e = 0; e < E_SZ; e++) {
        const float* W_e = W + (size_t)e * D_K * U_SZ;

        // acc initialized with bias (same per row)
        unsigned long long acc[8][4];
        {
            const float4* bp = reinterpret_cast<const float4*>(bias + (size_t)e * U_SZ + cg8);
            float4 bA = __ldg(bp);
            float4 bB = __ldg(bp + 1);
            unsigned long long p0 = pack2(bA.x, bA.y), p1 = pack2(bA.z, bA.w);
            unsigned long long p2 = pack2(bB.x, bB.y), p3 = pack2(bB.z, bB.w);
#pragma unroll
            for (int i = 0; i < 8; i++) { acc[i][0] = p0; acc[i][1] = p1; acc[i][2] = p2; acc[i][3] = p3; }
        }

        // K mainloop, double-buffered cp.async
        issue_chunk(W_e, X, b0, 0, 0, tid, sbase);
        for (int c = 0; c < NCHUNK; c++) {
            const int buf = c & 1;
            if (c + 1 < NCHUNK) {
                issue_chunk(W_e, X, b0, (c + 1) * KC, buf ^ 1, tid, sbase);
                cp_wait<1>();
            } else {
                cp_wait<0>();
            }
            __syncthreads();                 // chunk c visible to all
            compute_chunk(smem, buf, rg8, cg8, acc);
            __syncthreads();                 // buf free for chunk c+2's issue
        }

        // ---- Epilogue: softmax over U (no max-subtraction needed: logits ~ N(0,1)) ----
        float ev[8][8];
#pragma unroll
        for (int i = 0; i < 8; i++) {
#pragma unroll
            for (int j = 0; j < 4; j++) {
                float lo, hi;
                unpack2(acc[i][j], lo, hi);
                ev[i][2 * j]     = __expf(lo);
                ev[i][2 * j + 1] = __expf(hi);
            }
        }
        // Row sums: warp shfl reduce, then 4 warp-partials per row via smem
#pragma unroll
        for (int i = 0; i < 8; i++) {
            float s = ev[i][0] + ev[i][1] + ev[i][2] + ev[i][3]
                    + ev[i][4] + ev[i][5] + ev[i][6] + ev[i][7];
            s += __shfl_down_sync(0xFFFFFFFFu, s, 16);
            s += __shfl_down_sync(0xFFFFFFFFu, s, 8);
            s += __shfl_down_sync(0xFFFFFFFFu, s, 4);
            s += __shfl_down_sync(0xFFFFFFFFu, s, 2);
            s += __shfl_down_sync(0xFFFFFFFFu, s, 1);
            if (lane == 0) smem[RED_OFF + (rg8 + i) * 4 + warpLocal] = s;
        }
        __syncthreads();
        // Accumulate tp[b,e] * exp(l)/Z into the smem out accumulator
#pragma unroll
        for (int i = 0; i < 8; i++) {
            const int r = rg8 + i;
            const float Z = smem[RED_OFF + r * 4 + 0] + smem[RED_OFF + r * 4 + 1]
                          + smem[RED_OFF + r * 4 + 2] + smem[RED_OFF + r * 4 + 3];
            const float scale = smem[TP_OFF + r * E_SZ + e] / Z;
            float* oa = smem + OUT_OFF + r * U_SZ + cg8;
            float4 o0 = *reinterpret_cast<float4*>(oa);
            float4 o1 = *reinterpret_cast<float4*>(oa + 4);
            o0.x += scale * ev[i][0]; o0.y += scale * ev[i][1];
            o0.z += scale * ev[i][2]; o0.w += scale * ev[i][3];
            o1.x += scale * ev[i][4]; o1.y += scale * ev[i][5];
            o1.z += scale * ev[i][6]; o1.w += scale * ev[i][7];
            *reinterpret_cast<float4*>(oa)     = o0;
            *reinterpret_cast<float4*>(oa + 4) = o1;
        }
        __syncthreads();
    }

    // Write the 32x1024 tile (contiguous in the global output)
    float* og = out + (size_t)b0 * U_SZ;
    for (int i = tid * 4; i < TB * U_SZ; i += THREADS * 4)
        *reinterpret_cast<float4*>(og + i) =
            *reinterpret_cast<const float4*>(smem + OUT_OFF + i);
}

extern "C" void kernel_launch(void* const* d_in, const int* in_sizes, int n_in,
                              void* d_out, int out_size) {
    (void)in_sizes; (void)n_in; (void)out_size;
    const float* X    = (const float*)d_in[0];  // inputs    [B, D]
    const float* tp   = (const float*)d_in[1];  // type_prob [B, E, 1]
    const float* W    = (const float*)d_in[2];  // W         [E, D, U]
    const float* bias = (const float*)d_in[3];  // b         [E, U]
    float* out = (float*)d_out;                 // [B, U] fp32

    cudaFuncSetAttribute(projection_fused_kernel,
                         cudaFuncAttributeMaxDynamicSharedMemorySize,
                         (int)SMEM_BYTES);
    projection_fused_kernel<<<B_SZ / TB, THREADS, SMEM_BYTES>>>(X, tp, W, bias, out);
}

// round 3
// speedup vs baseline: 2.9553x; 2.9553x over previous
#include <cuda_runtime.h>
#include <cuda_bf16.h>
#include <cuda_fp16.h>
#include <cstdint>

// ----------------------------------------------------------------------------
// Problem constants
#define B_SZ  8192
#define D_K   1024
#define U_SZ  1024
#define E_SZ  16

// GEMM tile config
constexpr int TM = 128;               // batch rows per CTA
constexpr int TN = 256;               // U cols per CTA
constexpr int KC = 64;                // K per SMEM stage (bf16: 128B rows, SW128)
constexpr int NKT = D_K / KC;         // 16
constexpr int ATHREADS = 256;         // 8 warps

// ----------------------------------------------------------------------------
// Static device scratch (allocation-free rule)
__device__ __nv_bfloat16 g_Xhi[(size_t)B_SZ * D_K];
__device__ __nv_bfloat16 g_Xlo[(size_t)B_SZ * D_K];
__device__ __nv_bfloat16 g_Wthi[(size_t)E_SZ * U_SZ * D_K];   // [e][u][d]
__device__ __nv_bfloat16 g_Wtlo[(size_t)E_SZ * U_SZ * D_K];
__device__ __half        g_P[(size_t)E_SZ * B_SZ * U_SZ];     // exp(logits), fp16
__device__ float         g_S[(size_t)E_SZ * B_SZ];            // row sums Z

// ----------------------------------------------------------------------------
// Helpers (all legal on base compute_100: sm_75/80-era instructions)
__device__ __forceinline__ uint32_t smem_u32(const void* p) {
    return (uint32_t)__cvta_generic_to_shared(p);
}
__device__ __forceinline__ void cp16(uint32_t dst, const void* src) {
    asm volatile("cp.async.cg.shared.global [%0], [%1], 16;" :: "r"(dst), "l"(src));
}
__device__ __forceinline__ void cp_commit() {
    asm volatile("cp.async.commit_group;" ::: "memory");
}
template <int N> __device__ __forceinline__ void cp_wait() {
    asm volatile("cp.async.wait_group %0;" :: "n"(N) : "memory");
}
__device__ __forceinline__ void ldsm4(uint32_t* r, uint32_t addr) {
    asm volatile("ldmatrix.sync.aligned.m8n8.x4.shared.b16 {%0,%1,%2,%3}, [%4];"
                 : "=r"(r[0]), "=r"(r[1]), "=r"(r[2]), "=r"(r[3]) : "r"(addr));
}
__device__ __forceinline__ void mma_bf16(float* c, const uint32_t* a, uint32_t b0, uint32_t b1) {
    asm volatile("mma.sync.aligned.m16n8k16.row.col.f32.bf16.bf16.f32 "
                 "{%0,%1,%2,%3}, {%4,%5,%6,%7}, {%8,%9}, {%0,%1,%2,%3};"
                 : "+f"(c[0]), "+f"(c[1]), "+f"(c[2]), "+f"(c[3])
                 : "r"(a[0]), "r"(a[1]), "r"(a[2]), "r"(a[3]), "r"(b0), "r"(b1));
}
__device__ __forceinline__ uint32_t swz128(uint32_t off) { return off ^ ((off >> 3) & 0x70); }
__device__ __forceinline__ uint32_t pack_h2(float a, float b) {
    __half2 h = __floats2half2_rn(a, b);
    return *reinterpret_cast<uint32_t*>(&h);
}

// ----------------------------------------------------------------------------
// SMEM layout of GEMM kernel (bytes)
constexpr int SM_BIAS  = 0;                     // 256 floats
constexpr int SM_SROW  = 1024;                  // 128 floats
constexpr int SM_STAGE = 2048;                  // 1024-aligned
constexpr int A_BYTES  = TM * 128;              // 16KB per (hi|lo) A tile
constexpr int B_BYTES  = TN * 128;              // 32KB per (hi|lo) B tile
constexpr int STAGE_BYTES = 2 * A_BYTES + 2 * B_BYTES;   // 96KB
constexpr int SMEM_TOTAL  = SM_STAGE + 2 * STAGE_BYTES;  // 198656B

// ----------------------------------------------------------------------------
// Kernel 1: split X into bf16 hi/lo; zero S
__global__ void split_x_kernel(const float* __restrict__ X) {
    size_t i = (size_t)blockIdx.x * blockDim.x + threadIdx.x;
    float v = X[i];
    __nv_bfloat16 hi = __float2bfloat16(v);
    __nv_bfloat16 lo = __float2bfloat16(v - __bfloat162float(hi));
    g_Xhi[i] = hi;
    g_Xlo[i] = lo;
    if (i < (size_t)E_SZ * B_SZ) g_S[i] = 0.0f;
}

// Kernel 2: transpose + split W: [e][d][u] -> Wt[e][u][d] (hi/lo bf16)
__global__ void split_w_kernel(const float* __restrict__ W) {
    __shared__ float t[32][33];
    const int u0 = blockIdx.x * 32;
    const int d0 = blockIdx.y * 32;
    const int e  = blockIdx.z;
    const int tx = threadIdx.x, ty = threadIdx.y;
#pragma unroll
    for (int i = 0; i < 4; i++) {
        int d = d0 + ty + i * 8;
        t[ty + i * 8][tx] = W[((size_t)e * D_K + d) * U_SZ + u0 + tx];
    }
    __syncthreads();
#pragma unroll
    for (int i = 0; i < 4; i++) {
        int u = u0 + ty + i * 8;
        float v = t[tx][ty + i * 8];
        __nv_bfloat16 hi = __float2bfloat16(v);
        __nv_bfloat16 lo = __float2bfloat16(v - __bfloat162float(hi));
        size_t idx = ((size_t)e * U_SZ + u) * D_K + d0 + tx;
        g_Wthi[idx] = hi;
        g_Wtlo[idx] = lo;
    }
}

// ----------------------------------------------------------------------------
// Kernel 3: batched GEMM (3x bf16 split, HMMA) + exp + row-sum
// grid: (U/TN = 4, B/TM = 64, E = 16), 256 threads
__global__ void __launch_bounds__(ATHREADS, 1)
gemm_exp_kernel(const float* __restrict__ bias) {
    extern __shared__ char smem[];
    const uint32_t sb = smem_u32(smem);
    const int tid  = threadIdx.x;
    const int lane = tid & 31;
    const int wid  = tid >> 5;
    const int warp_m = wid >> 2;       // 0..1  (64-row slab)
    const int warp_n = wid & 3;        // 0..3  (64-col slab)
    const int n0 = blockIdx.x * TN;
    const int b0 = blockIdx.y * TM;
    const int e  = blockIdx.z;

    float* biasS = reinterpret_cast<float*>(smem + SM_BIAS);
    float* srowS = reinterpret_cast<float*>(smem + SM_SROW);
    biasS[tid] = bias[(size_t)e * U_SZ + n0 + tid];
    if (tid < TM) srowS[tid] = 0.0f;

    const __nv_bfloat16* gAhi = g_Xhi + (size_t)b0 * D_K;
    const __nv_bfloat16* gAlo = g_Xlo + (size_t)b0 * D_K;
    const __nv_bfloat16* gBhi = g_Wthi + ((size_t)e * U_SZ + n0) * D_K;
    const __nv_bfloat16* gBlo = g_Wtlo + ((size_t)e * U_SZ + n0) * D_K;

    auto load_tile = [&](int kt, int stage) {
        const int k0 = kt * KC;
        const uint32_t base = sb + SM_STAGE + stage * STAGE_BYTES;
#pragma unroll
        for (int t = 0; t < 4; t++) {            // A hi+lo: 1024 16B units each
            int uid = tid + t * ATHREADS;
            int row = uid >> 3, c8 = uid & 7;
            uint32_t soff = swz128((uint32_t)(row * 128 + c8 * 16));
            cp16(base + soff,            gAhi + (size_t)row * D_K + k0 + c8 * 8);
            cp16(base + A_BYTES + soff,  gAlo + (size_t)row * D_K + k0 + c8 * 8);
        }
#pragma unroll
        for (int t = 0; t < 8; t++) {            // B hi+lo: 2048 units each
            int uid = tid + t * ATHREADS;
            int row = uid >> 3, c8 = uid & 7;
            uint32_t soff = swz128((uint32_t)(row * 128 + c8 * 16));
            cp16(base + 2 * A_BYTES + soff,           gBhi + (size_t)row * D_K + k0 + c8 * 8);
            cp16(base + 2 * A_BYTES + B_BYTES + soff, gBlo + (size_t)row * D_K + k0 + c8 * 8);
        }
        cp_commit();
    };

    float acc[4][8][4];
#pragma unroll
    for (int mi = 0; mi < 4; mi++)
#pragma unroll
        for (int nf = 0; nf < 8; nf++)
#pragma unroll
            for (int q = 0; q < 4; q++) acc[mi][nf][q] = 0.0f;

    load_tile(0, 0);
    for (int kt = 0; kt < NKT; kt++) {
        const int cur = kt & 1;
        if (kt + 1 < NKT) { load_tile(kt + 1, cur ^ 1); cp_wait<1>(); }
        else              { cp_wait<0>(); }
        __syncthreads();

        const uint32_t stage = sb + SM_STAGE + cur * STAGE_BYTES;
#pragma unroll
        for (int s = 0; s < 4; s++) {            // 4 x k16 sub-steps in KC=64
            const uint32_t colb = (uint32_t)(s * 32 + (lane >> 4) * 16);
            uint32_t ah[4][4], al[4][4], bh[4][4], bl[4][4];
#pragma unroll
            for (int mi = 0; mi < 4; mi++) {
                uint32_t off = swz128((uint32_t)((warp_m * 64 + mi * 16 + (lane & 15)) * 128) + colb);
                ldsm4(ah[mi], stage + off);
                ldsm4(al[mi], stage + A_BYTES + off);
            }
#pragma unroll
            for (int nj = 0; nj < 4; nj++) {
                uint32_t off = swz128((uint32_t)((warp_n * 64 + nj * 16 + (lane & 15)) * 128) + colb);
                ldsm4(bh[nj], stage + 2 * A_BYTES + off);
                ldsm4(bl[nj], stage + 2 * A_BYTES + B_BYTES + off);
            }
#pragma unroll
            for (int mi = 0; mi < 4; mi++) {
#pragma unroll
                for (int nf = 0; nf < 8; nf++) {
                    const int nj = nf >> 1, p = nf & 1;
                    const uint32_t b0h = bh[nj][p], b1h = bh[nj][p + 2];
                    const uint32_t b0l = bl[nj][p], b1l = bl[nj][p + 2];
                    mma_bf16(acc[mi][nf], ah[mi], b0h, b1h);   // hi*hi
                    mma_bf16(acc[mi][nf], ah[mi], b0l, b1l);   // hi*lo
                    mma_bf16(acc[mi][nf], al[mi], b0h, b1h);   // lo*hi
                }
            }
        }
        __syncthreads();
    }

    // ---- Epilogue: +bias, exp, fp16 store, row sums ----
    const int g  = lane >> 2;     // row within frag
    const int t4 = lane & 3;      // col pair within frag
    __half* Pe = g_P + ((size_t)e * B_SZ) * U_SZ;

#pragma unroll
    for (int mi = 0; mi < 4; mi++) {
        const int r_lo = warp_m * 64 + mi * 16 + g;
        const int r_hi = r_lo + 8;
        float s_lo = 0.0f, s_hi = 0.0f;
        uint32_t* row_lo = reinterpret_cast<uint32_t*>(Pe + (size_t)(b0 + r_lo) * U_SZ + n0);
        uint32_t* row_hi = reinterpret_cast<uint32_t*>(Pe + (size_t)(b0 + r_hi) * U_SZ + n0);
#pragma unroll
        for (int nf = 0; nf < 8; nf++) {
            const int col = warp_n * 64 + nf * 8 + t4 * 2;
            const float bz0 = biasS[col], bz1 = biasS[col + 1];
            float e00 = __expf(acc[mi][nf][0] + bz0);
            float e01 = __expf(acc[mi][nf][1] + bz1);
            float e10 = __expf(acc[mi][nf][2] + bz0);
            float e11 = __expf(acc[mi][nf][3] + bz1);
            s_lo += e00 + e01;
            s_hi += e10 + e11;
            row_lo[col >> 1] = pack_h2(e00, e01);
            row_hi[col >> 1] = pack_h2(e10, e11);
        }
        s_lo += __shfl_xor_sync(0xFFFFFFFFu, s_lo, 1);
        s_lo += __shfl_xor_sync(0xFFFFFFFFu, s_lo, 2);
        s_hi += __shfl_xor_sync(0xFFFFFFFFu, s_hi, 1);
        s_hi += __shfl_xor_sync(0xFFFFFFFFu, s_hi, 2);
        if (t4 == 0) {
            atomicAdd(&srowS[r_lo], s_lo);
            atomicAdd(&srowS[r_hi], s_hi);
        }
    }
    __syncthreads();
    if (tid < TM) atomicAdd(&g_S[(size_t)e * B_SZ + b0 + tid], srowS[tid]);
}

// ----------------------------------------------------------------------------
// Kernel 4: out[b][u] = sum_e tp[b][e]/S[e][b] * P[e][b][u]
__global__ void combine_kernel(const float* __restrict__ tp, float* __restrict__ out) {
    const int b = blockIdx.x;
    __shared__ float c[E_SZ];
    if (threadIdx.x < E_SZ)
        c[threadIdx.x] = tp[(size_t)b * E_SZ + threadIdx.x]
                       / g_S[(size_t)threadIdx.x * B_SZ + b];
    __syncthreads();
    const int u0 = threadIdx.x * 4;
    float a0 = 0.f, a1 = 0.f, a2 = 0.f, a3 = 0.f;
#pragma unroll
    for (int e = 0; e < E_SZ; e++) {
        const uint2 q = *reinterpret_cast<const uint2*>(
            g_P + ((size_t)e * B_SZ + b) * U_SZ + u0);
        __half2 h0 = *reinterpret_cast<const __half2*>(&q.x);
        __half2 h1 = *reinterpret_cast<const __half2*>(&q.y);
        float2 f0 = __half22float2(h0);
        float2 f1 = __half22float2(h1);
        const float ce = c[e];
        a0 += ce * f0.x; a1 += ce * f0.y; a2 += ce * f1.x; a3 += ce * f1.y;
    }
    *reinterpret_cast<float4*>(out + (size_t)b * U_SZ + u0) = make_float4(a0, a1, a2, a3);
}

// ----------------------------------------------------------------------------
extern "C" void kernel_launch(void* const* d_in, const int* in_sizes, int n_in,
                              void* d_out, int out_size) {
    (void)in_sizes; (void)n_in; (void)out_size;
    const float* X    = (const float*)d_in[0];  // [B, D]
    const float* tp   = (const float*)d_in[1];  // [B, E, 1]
    const float* W    = (const float*)d_in[2];  // [E, D, U]
    const float* bias = (const float*)d_in[3];  // [E, U]
    float* out = (float*)d_out;

    cudaFuncSetAttribute(gemm_exp_kernel,
                         cudaFuncAttributeMaxDynamicSharedMemorySize, SMEM_TOTAL);

    split_x_kernel<<<(B_SZ * D_K) / 256, 256>>>(X);
    split_w_kernel<<<dim3(U_SZ / 32, D_K / 32, E_SZ), dim3(32, 8)>>>(W);
    gemm_exp_kernel<<<dim3(U_SZ / TN, B_SZ / TM, E_SZ), ATHREADS, SMEM_TOTAL>>>(bias);
    combine_kernel<<<B_SZ, 256>>>(tp, out);
}

// round 5
// speedup vs baseline: 4.1781x; 1.4137x over previous
#include <cuda_runtime.h>
#include <cuda_bf16.h>
#include <cuda_fp16.h>
#include <cstdint>

// ----------------------------------------------------------------------------
// Problem constants
#define B_SZ  8192
#define D_K   1024
#define U_SZ  1024
#define E_SZ  16

// GEMM tile config
constexpr int TM = 128;               // batch rows per CTA
constexpr int TN = 256;               // U cols per CTA
constexpr int KC = 32;                // K per SMEM stage (fp32/tf32: 128B rows)
constexpr int NKT = D_K / KC;         // 32
constexpr int ATHREADS = 256;         // 8 warps

// ----------------------------------------------------------------------------
// Static device scratch (allocation-free rule)
__device__ float  g_Xr[(size_t)B_SZ * D_K];              // tf32-rounded X
__device__ float  g_Wt[(size_t)E_SZ * U_SZ * D_K];       // tf32-rounded W^T [e][u][d]
__device__ __half g_P[(size_t)E_SZ * B_SZ * U_SZ];       // exp(logits), fp16
__device__ float  g_S[(size_t)E_SZ * B_SZ];              // row sums Z

// ----------------------------------------------------------------------------
// Helpers (all legal on base compute_100)
__device__ __forceinline__ uint32_t smem_u32(const void* p) {
    return (uint32_t)__cvta_generic_to_shared(p);
}
__device__ __forceinline__ void cp16(uint32_t dst, const void* src) {
    asm volatile("cp.async.cg.shared.global [%0], [%1], 16;" :: "r"(dst), "l"(src));
}
__device__ __forceinline__ void cp_commit() {
    asm volatile("cp.async.commit_group;" ::: "memory");
}
template <int N> __device__ __forceinline__ void cp_wait() {
    asm volatile("cp.async.wait_group %0;" :: "n"(N) : "memory");
}
__device__ __forceinline__ uint32_t lds32(uint32_t addr) {
    uint32_t v;
    asm volatile("ld.shared.b32 %0, [%1];" : "=r"(v) : "r"(addr));
    return v;
}
__device__ __forceinline__ void mma_tf32(float* c, const uint32_t* a, uint32_t b0, uint32_t b1) {
    asm volatile("mma.sync.aligned.m16n8k8.row.col.f32.tf32.tf32.f32 "
                 "{%0,%1,%2,%3}, {%4,%5,%6,%7}, {%8,%9}, {%0,%1,%2,%3};"
                 : "+f"(c[0]), "+f"(c[1]), "+f"(c[2]), "+f"(c[3])
                 : "r"(a[0]), "r"(a[1]), "r"(a[2]), "r"(a[3]), "r"(b0), "r"(b1));
}
// tf32 cvt: destination must be a .b32 register (bit pattern of the rounded value)
__device__ __forceinline__ float round_tf32(float v) {
    uint32_t r;
    asm("cvt.rna.tf32.f32 %0, %1;" : "=r"(r) : "f"(v));
    return __uint_as_float(r);
}
__device__ __forceinline__ uint32_t swz128(uint32_t off) { return off ^ ((off >> 3) & 0x70); }
__device__ __forceinline__ uint32_t pack_h2(float a, float b) {
    __half2 h = __floats2half2_rn(a, b);
    return *reinterpret_cast<uint32_t*>(&h);
}

// ----------------------------------------------------------------------------
// SMEM layout of GEMM kernel (bytes)
constexpr int SM_BIAS  = 0;                      // 256 floats
constexpr int SM_SROW  = 1024;                   // 128 floats
constexpr int SM_STAGE = 2048;                   // 1024-aligned
constexpr int A_BYTES  = TM * 128;               // 16KB  (128 rows x 32 fp32)
constexpr int B_BYTES  = TN * 128;               // 32KB  (256 rows x 32 fp32)
constexpr int STAGE_BYTES = A_BYTES + B_BYTES;   // 48KB
constexpr int SMEM_TOTAL  = SM_STAGE + 2 * STAGE_BYTES;  // 100352B

// ----------------------------------------------------------------------------
// Kernel 1: round X to tf32 grid; zero S
__global__ void round_x_kernel(const float* __restrict__ X) {
    size_t i = (size_t)blockIdx.x * blockDim.x + threadIdx.x;
    g_Xr[i] = round_tf32(X[i]);
    if (i < (size_t)E_SZ * B_SZ) g_S[i] = 0.0f;
}

// Kernel 2: transpose + round W: [e][d][u] -> Wt[e][u][d]
__global__ void round_w_kernel(const float* __restrict__ W) {
    __shared__ float t[32][33];
    const int u0 = blockIdx.x * 32;
    const int d0 = blockIdx.y * 32;
    const int e  = blockIdx.z;
    const int tx = threadIdx.x, ty = threadIdx.y;
#pragma unroll
    for (int i = 0; i < 4; i++) {
        int d = d0 + ty + i * 8;
        t[ty + i * 8][tx] = W[((size_t)e * D_K + d) * U_SZ + u0 + tx];
    }
    __syncthreads();
#pragma unroll
    for (int i = 0; i < 4; i++) {
        int u = u0 + ty + i * 8;
        g_Wt[((size_t)e * U_SZ + u) * D_K + d0 + tx] = round_tf32(t[tx][ty + i * 8]);
    }
}

// ----------------------------------------------------------------------------
// Kernel 3: batched GEMM (single-pass tf32 HMMA) + exp + row-sum
// grid: (U/TN = 4, B/TM = 64, E = 16), 256 threads
__global__ void __launch_bounds__(ATHREADS, 1)
gemm_exp_kernel(const float* __restrict__ bias) {
    extern __shared__ char smem[];
    const uint32_t sb = smem_u32(smem);
    const int tid  = threadIdx.x;
    const int lane = tid & 31;
    const int wid  = tid >> 5;
    const int warp_m = wid >> 2;       // 0..1  (64-row slab)
    const int warp_n = wid & 3;        // 0..3  (64-col slab)
    const int g  = lane >> 2;          // 0..7
    const int t4 = lane & 3;           // 0..3
    const int n0 = blockIdx.x * TN;
    const int b0 = blockIdx.y * TM;
    const int e  = blockIdx.z;

    float* biasS = reinterpret_cast<float*>(smem + SM_BIAS);
    float* srowS = reinterpret_cast<float*>(smem + SM_SROW);
    biasS[tid] = bias[(size_t)e * U_SZ + n0 + tid];
    if (tid < TM) srowS[tid] = 0.0f;

    const float* gA = g_Xr + (size_t)b0 * D_K;
    const float* gB = g_Wt + ((size_t)e * U_SZ + n0) * D_K;

    auto load_tile = [&](int kt, int stage) {
        const int k0 = kt * KC;
        const uint32_t base = sb + SM_STAGE + stage * STAGE_BYTES;
#pragma unroll
        for (int t = 0; t < 4; t++) {            // A: 1024 16B granules
            int uid = tid + t * ATHREADS;
            int row = uid >> 3, gr = uid & 7;
            cp16(base + swz128((uint32_t)(row * 128 + gr * 16)),
                 gA + (size_t)row * D_K + k0 + gr * 4);
        }
#pragma unroll
        for (int t = 0; t < 8; t++) {            // B: 2048 granules
            int uid = tid + t * ATHREADS;
            int row = uid >> 3, gr = uid & 7;
            cp16(base + A_BYTES + swz128((uint32_t)(row * 128 + gr * 16)),
                 gB + (size_t)row * D_K + k0 + gr * 4);
        }
        cp_commit();
    };

    float acc[4][8][4];
#pragma unroll
    for (int mi = 0; mi < 4; mi++)
#pragma unroll
        for (int nf = 0; nf < 8; nf++)
#pragma unroll
            for (int q = 0; q < 4; q++) acc[mi][nf][q] = 0.0f;

    load_tile(0, 0);
    for (int kt = 0; kt < NKT; kt++) {
        const int cur = kt & 1;
        if (kt + 1 < NKT) { load_tile(kt + 1, cur ^ 1); cp_wait<1>(); }
        else              { cp_wait<0>(); }
        __syncthreads();

        const uint32_t aBase = sb + SM_STAGE + cur * STAGE_BYTES;
        const uint32_t bBase = aBase + A_BYTES;
#pragma unroll
        for (int s = 0; s < 4; s++) {            // 4 x k8 sub-steps in KC=32
            const int c0 = s * 8 + t4;           // k-col of frag reg 0/1
            const int c1 = c0 + 4;               // k-col of frag reg 2/3 (b1)
            uint32_t a[4][4];
#pragma unroll
            for (int mi = 0; mi < 4; mi++) {
                const int r0 = warp_m * 64 + mi * 16 + g;
                const int r1 = r0 + 8;
                a[mi][0] = lds32(aBase + swz128((uint32_t)(r0 * 128 + c0 * 4)));
                a[mi][1] = lds32(aBase + swz128((uint32_t)(r1 * 128 + c0 * 4)));
                a[mi][2] = lds32(aBase + swz128((uint32_t)(r0 * 128 + c1 * 4)));
                a[mi][3] = lds32(aBase + swz128((uint32_t)(r1 * 128 + c1 * 4)));
            }
            uint32_t b[8][2];
#pragma unroll
            for (int nf = 0; nf < 8; nf++) {
                const int n = warp_n * 64 + nf * 8 + g;
                b[nf][0] = lds32(bBase + swz128((uint32_t)(n * 128 + c0 * 4)));
                b[nf][1] = lds32(bBase + swz128((uint32_t)(n * 128 + c1 * 4)));
            }
#pragma unroll
            for (int mi = 0; mi < 4; mi++)
#pragma unroll
                for (int nf = 0; nf < 8; nf++)
                    mma_tf32(acc[mi][nf], a[mi], b[nf][0], b[nf][1]);
        }
        __syncthreads();
    }

    // ---- Epilogue: +bias, exp, fp16 store, row sums ----
    __half* Pe = g_P + ((size_t)e * B_SZ) * U_SZ;
#pragma unroll
    for (int mi = 0; mi < 4; mi++) {
        const int r_lo = warp_m * 64 + mi * 16 + g;
        const int r_hi = r_lo + 8;
        float s_lo = 0.0f, s_hi = 0.0f;
        uint32_t* row_lo = reinterpret_cast<uint32_t*>(Pe + (size_t)(b0 + r_lo) * U_SZ + n0);
        uint32_t* row_hi = reinterpret_cast<uint32_t*>(Pe + (size_t)(b0 + r_hi) * U_SZ + n0);
#pragma unroll
        for (int nf = 0; nf < 8; nf++) {
            const int col = warp_n * 64 + nf * 8 + t4 * 2;
            const float bz0 = biasS[col], bz1 = biasS[col + 1];
            float e00 = __expf(acc[mi][nf][0] + bz0);
            float e01 = __expf(acc[mi][nf][1] + bz1);
            float e10 = __expf(acc[mi][nf][2] + bz0);
            float e11 = __expf(acc[mi][nf][3] + bz1);
            s_lo += e00 + e01;
            s_hi += e10 + e11;
            row_lo[col >> 1] = pack_h2(e00, e01);
            row_hi[col >> 1] = pack_h2(e10, e11);
        }
        s_lo += __shfl_xor_sync(0xFFFFFFFFu, s_lo, 1);
        s_lo += __shfl_xor_sync(0xFFFFFFFFu, s_lo, 2);
        s_hi += __shfl_xor_sync(0xFFFFFFFFu, s_hi, 1);
        s_hi += __shfl_xor_sync(0xFFFFFFFFu, s_hi, 2);
        if (t4 == 0) {
            atomicAdd(&srowS[r_lo], s_lo);
            atomicAdd(&srowS[r_hi], s_hi);
        }
    }
    __syncthreads();
    if (tid < TM) atomicAdd(&g_S[(size_t)e * B_SZ + b0 + tid], srowS[tid]);
}

// ----------------------------------------------------------------------------
// Kernel 4: out[b][u] = sum_e tp[b][e]/S[e][b] * P[e][b][u]
__global__ void combine_kernel(const float* __restrict__ tp, float* __restrict__ out) {
    const int b = blockIdx.x;
    __shared__ float c[E_SZ];
    if (threadIdx.x < E_SZ)
        c[threadIdx.x] = tp[(size_t)b * E_SZ + threadIdx.x]
                       / g_S[(size_t)threadIdx.x * B_SZ + b];
    __syncthreads();
    const int u0 = threadIdx.x * 4;
    float a0 = 0.f, a1 = 0.f, a2 = 0.f, a3 = 0.f;
#pragma unroll
    for (int e = 0; e < E_SZ; e++) {
        const uint2 q = *reinterpret_cast<const uint2*>(
            g_P + ((size_t)e * B_SZ + b) * U_SZ + u0);
        __half2 h0 = *reinterpret_cast<const __half2*>(&q.x);
        __half2 h1 = *reinterpret_cast<const __half2*>(&q.y);
        float2 f0 = __half22float2(h0);
        float2 f1 = __half22float2(h1);
        const float ce = c[e];
        a0 += ce * f0.x; a1 += ce * f0.y; a2 += ce * f1.x; a3 += ce * f1.y;
    }
    *reinterpret_cast<float4*>(out + (size_t)b * U_SZ + u0) = make_float4(a0, a1, a2, a3);
}

// ----------------------------------------------------------------------------
extern "C" void kernel_launch(void* const* d_in, const int* in_sizes, int n_in,
                              void* d_out, int out_size) {
    (void)in_sizes; (void)n_in; (void)out_size;
    const float* X    = (const float*)d_in[0];  // [B, D]
    const float* tp   = (const float*)d_in[1];  // [B, E, 1]
    const float* W    = (const float*)d_in[2];  // [E, D, U]
    const float* bias = (const float*)d_in[3];  // [E, U]
    float* out = (float*)d_out;

    cudaFuncSetAttribute(gemm_exp_kernel,
                         cudaFuncAttributeMaxDynamicSharedMemorySize, SMEM_TOTAL);

    round_x_kernel<<<(B_SZ * D_K) / 256, 256>>>(X);
    round_w_kernel<<<dim3(U_SZ / 32, D_K / 32, E_SZ), dim3(32, 8)>>>(W);
    gemm_exp_kernel<<<dim3(U_SZ / TN, B_SZ / TM, E_SZ), ATHREADS, SMEM_TOTAL>>>(bias);
    combine_kernel<<<B_SZ, 256>>>(tp, out);
}

// round 6
// speedup vs baseline: 7.2540x; 1.7362x over previous
#include <cuda_runtime.h>
#include <cuda_fp16.h>
#include <cstdint>

// ----------------------------------------------------------------------------
// Problem constants
#define B_SZ  8192
#define D_K   1024
#define U_SZ  1024
#define E_SZ  16

// GEMM tile config
constexpr int TM = 128;               // batch rows per CTA
constexpr int TN = 256;               // U cols per CTA
constexpr int KC = 64;                // K per SMEM stage (fp16: 128B rows)
constexpr int NKT = D_K / KC;         // 16
constexpr int NSTAGE = 3;
constexpr int ATHREADS = 256;         // 8 warps

// ----------------------------------------------------------------------------
// Static device scratch (allocation-free rule)
__device__ __half g_Xh[(size_t)B_SZ * D_K];              // fp16 X
__device__ __half g_Wth[(size_t)E_SZ * U_SZ * D_K];      // fp16 W^T [e][u][d]
__device__ __half g_P[(size_t)E_SZ * B_SZ * U_SZ];       // exp(logits), fp16
__device__ float  g_S[(size_t)E_SZ * B_SZ];              // row sums Z

// ----------------------------------------------------------------------------
// Helpers (all legal on base compute_100)
__device__ __forceinline__ uint32_t smem_u32(const void* p) {
    return (uint32_t)__cvta_generic_to_shared(p);
}
__device__ __forceinline__ void cp16(uint32_t dst, const void* src) {
    asm volatile("cp.async.cg.shared.global [%0], [%1], 16;" :: "r"(dst), "l"(src));
}
__device__ __forceinline__ void cp_commit() {
    asm volatile("cp.async.commit_group;" ::: "memory");
}
template <int N> __device__ __forceinline__ void cp_wait() {
    asm volatile("cp.async.wait_group %0;" :: "n"(N) : "memory");
}
__device__ __forceinline__ void ldsm4(uint32_t* r, uint32_t addr) {
    asm volatile("ldmatrix.sync.aligned.m8n8.x4.shared.b16 {%0,%1,%2,%3}, [%4];"
                 : "=r"(r[0]), "=r"(r[1]), "=r"(r[2]), "=r"(r[3]) : "r"(addr));
}
__device__ __forceinline__ void mma_f16(float* c, const uint32_t* a, uint32_t b0, uint32_t b1) {
    asm volatile("mma.sync.aligned.m16n8k16.row.col.f32.f16.f16.f32 "
                 "{%0,%1,%2,%3}, {%4,%5,%6,%7}, {%8,%9}, {%0,%1,%2,%3};"
                 : "+f"(c[0]), "+f"(c[1]), "+f"(c[2]), "+f"(c[3])
                 : "r"(a[0]), "r"(a[1]), "r"(a[2]), "r"(a[3]), "r"(b0), "r"(b1));
}
__device__ __forceinline__ uint32_t swz128(uint32_t off) { return off ^ ((off >> 3) & 0x70); }
__device__ __forceinline__ uint32_t pack_h2(float a, float b) {
    __half2 h = __floats2half2_rn(a, b);
    return *reinterpret_cast<uint32_t*>(&h);
}

// ----------------------------------------------------------------------------
// SMEM layout of GEMM kernel (bytes)
constexpr int SM_BIAS  = 0;                      // 256 floats
constexpr int SM_SROW  = 1024;                   // 128 floats
constexpr int SM_STAGE = 2048;                   // 1024-aligned
constexpr int A_BYTES  = TM * 128;               // 16KB  (128 rows x 64 fp16)
constexpr int B_BYTES  = TN * 128;               // 32KB  (256 rows x 64 fp16)
constexpr int STAGE_BYTES = A_BYTES + B_BYTES;   // 48KB
constexpr int SMEM_TOTAL  = SM_STAGE + NSTAGE * STAGE_BYTES;  // 149504B

// ----------------------------------------------------------------------------
// Kernel 1: convert X to fp16; zero S
__global__ void conv_x_kernel(const float* __restrict__ X) {
    size_t i = (size_t)blockIdx.x * blockDim.x + threadIdx.x;
    g_Xh[i] = __float2half_rn(X[i]);
    if (i < (size_t)E_SZ * B_SZ) g_S[i] = 0.0f;
}

// Kernel 2: transpose + convert W: [e][d][u] -> Wt[e][u][d] fp16
__global__ void conv_w_kernel(const float* __restrict__ W) {
    __shared__ float t[32][33];
    const int u0 = blockIdx.x * 32;
    const int d0 = blockIdx.y * 32;
    const int e  = blockIdx.z;
    const int tx = threadIdx.x, ty = threadIdx.y;
#pragma unroll
    for (int i = 0; i < 4; i++) {
        int d = d0 + ty + i * 8;
        t[ty + i * 8][tx] = W[((size_t)e * D_K + d) * U_SZ + u0 + tx];
    }
    __syncthreads();
#pragma unroll
    for (int i = 0; i < 4; i++) {
        int u = u0 + ty + i * 8;
        g_Wth[((size_t)e * U_SZ + u) * D_K + d0 + tx] = __float2half_rn(t[tx][ty + i * 8]);
    }
}

// ----------------------------------------------------------------------------
// Kernel 3: batched GEMM (single-pass fp16 HMMA k16) + exp + row-sum
// grid: (U/TN = 4, B/TM = 64, E = 16), 256 threads
__global__ void __launch_bounds__(ATHREADS, 1)
gemm_exp_kernel(const float* __restrict__ bias) {
    extern __shared__ char smem[];
    const uint32_t sb = smem_u32(smem);
    const int tid  = threadIdx.x;
    const int lane = tid & 31;
    const int wid  = tid >> 5;
    const int warp_m = wid >> 2;       // 0..1  (64-row slab)
    const int warp_n = wid & 3;        // 0..3  (64-col slab)
    const int g  = lane >> 2;          // 0..7
    const int t4 = lane & 3;           // 0..3
    const int n0 = blockIdx.x * TN;
    const int b0 = blockIdx.y * TM;
    const int e  = blockIdx.z;

    float* biasS = reinterpret_cast<float*>(smem + SM_BIAS);
    float* srowS = reinterpret_cast<float*>(smem + SM_SROW);
    biasS[tid] = bias[(size_t)e * U_SZ + n0 + tid];
    if (tid < TM) srowS[tid] = 0.0f;

    const __half* gA = g_Xh + (size_t)b0 * D_K;
    const __half* gB = g_Wth + ((size_t)e * U_SZ + n0) * D_K;

    auto load_tile = [&](int kt, int stage) {
        const int k0 = kt * KC;
        const uint32_t base = sb + SM_STAGE + stage * STAGE_BYTES;
#pragma unroll
        for (int t = 0; t < 4; t++) {            // A: 1024 16B granules
            int uid = tid + t * ATHREADS;
            int row = uid >> 3, gr = uid & 7;
            cp16(base + swz128((uint32_t)(row * 128 + gr * 16)),
                 gA + (size_t)row * D_K + k0 + gr * 8);
        }
#pragma unroll
        for (int t = 0; t < 8; t++) {            // B: 2048 granules
            int uid = tid + t * ATHREADS;
            int row = uid >> 3, gr = uid & 7;
            cp16(base + A_BYTES + swz128((uint32_t)(row * 128 + gr * 16)),
                 gB + (size_t)row * D_K + k0 + gr * 8);
        }
        cp_commit();
    };

    float acc[4][8][4];
#pragma unroll
    for (int mi = 0; mi < 4; mi++)
#pragma unroll
        for (int nf = 0; nf < 8; nf++)
#pragma unroll
            for (int q = 0; q < 4; q++) acc[mi][nf][q] = 0.0f;

    // 3-stage pipeline: one __syncthreads per K-tile
    load_tile(0, 0);
    load_tile(1, 1);
    for (int kt = 0; kt < NKT; kt++) {
        if (kt < NKT - 1) cp_wait<1>();
        else              cp_wait<0>();
        __syncthreads();                         // tile kt visible; stage (kt+2)%3 free
        if (kt + 2 < NKT) load_tile(kt + 2, (kt + 2) % NSTAGE);

        const uint32_t aBase = sb + SM_STAGE + (kt % NSTAGE) * STAGE_BYTES;
        const uint32_t bBase = aBase + A_BYTES;
#pragma unroll
        for (int s = 0; s < 4; s++) {            // 4 x k16 sub-steps in KC=64
            const uint32_t colb = (uint32_t)(s * 32 + (lane >> 4) * 16);
            uint32_t a[4][4], b[4][4];
#pragma unroll
            for (int mi = 0; mi < 4; mi++) {
                uint32_t off = swz128((uint32_t)((warp_m * 64 + mi * 16 + (lane & 15)) * 128) + colb);
                ldsm4(a[mi], aBase + off);
            }
#pragma unroll
            for (int nj = 0; nj < 4; nj++) {
                uint32_t off = swz128((uint32_t)((warp_n * 64 + nj * 16 + (lane & 15)) * 128) + colb);
                ldsm4(b[nj], bBase + off);
            }
#pragma unroll
            for (int mi = 0; mi < 4; mi++) {
#pragma unroll
                for (int nf = 0; nf < 8; nf++) {
                    const int nj = nf >> 1, p = nf & 1;
                    mma_f16(acc[mi][nf], a[mi], b[nj][p], b[nj][p + 2]);
                }
            }
        }
    }

    // ---- Epilogue: +bias, exp, fp16 store, row sums ----
    __half* Pe = g_P + ((size_t)e * B_SZ) * U_SZ;
#pragma unroll
    for (int mi = 0; mi < 4; mi++) {
        const int r_lo = warp_m * 64 + mi * 16 + g;
        const int r_hi = r_lo + 8;
        float s_lo = 0.0f, s_hi = 0.0f;
        uint32_t* row_lo = reinterpret_cast<uint32_t*>(Pe + (size_t)(b0 + r_lo) * U_SZ + n0);
        uint32_t* row_hi = reinterpret_cast<uint32_t*>(Pe + (size_t)(b0 + r_hi) * U_SZ + n0);
#pragma unroll
        for (int nf = 0; nf < 8; nf++) {
            const int col = warp_n * 64 + nf * 8 + t4 * 2;
            const float bz0 = biasS[col], bz1 = biasS[col + 1];
            float e00 = __expf(acc[mi][nf][0] + bz0);
            float e01 = __expf(acc[mi][nf][1] + bz1);
            float e10 = __expf(acc[mi][nf][2] + bz0);
            float e11 = __expf(acc[mi][nf][3] + bz1);
            s_lo += e00 + e01;
            s_hi += e10 + e11;
            row_lo[col >> 1] = pack_h2(e00, e01);
            row_hi[col >> 1] = pack_h2(e10, e11);
        }
        s_lo += __shfl_xor_sync(0xFFFFFFFFu, s_lo, 1);
        s_lo += __shfl_xor_sync(0xFFFFFFFFu, s_lo, 2);
        s_hi += __shfl_xor_sync(0xFFFFFFFFu, s_hi, 1);
        s_hi += __shfl_xor_sync(0xFFFFFFFFu, s_hi, 2);
        if (t4 == 0) {
            atomicAdd(&srowS[r_lo], s_lo);
            atomicAdd(&srowS[r_hi], s_hi);
        }
    }
    __syncthreads();
    if (tid < TM) atomicAdd(&g_S[(size_t)e * B_SZ + b0 + tid], srowS[tid]);
}

// ----------------------------------------------------------------------------
// Kernel 4: out[b][u] = sum_e tp[b][e]/S[e][b] * P[e][b][u]
__global__ void combine_kernel(const float* __restrict__ tp, float* __restrict__ out) {
    const int b = blockIdx.x;
    __shared__ float c[E_SZ];
    if (threadIdx.x < E_SZ)
        c[threadIdx.x] = tp[(size_t)b * E_SZ + threadIdx.x]
                       / g_S[(size_t)threadIdx.x * B_SZ + b];
    __syncthreads();
    const int u0 = threadIdx.x * 4;
    float a0 = 0.f, a1 = 0.f, a2 = 0.f, a3 = 0.f;
#pragma unroll
    for (int e = 0; e < E_SZ; e++) {
        const uint2 q = *reinterpret_cast<const uint2*>(
            g_P + ((size_t)e * B_SZ + b) * U_SZ + u0);
        __half2 h0 = *reinterpret_cast<const __half2*>(&q.x);
        __half2 h1 = *reinterpret_cast<const __half2*>(&q.y);
        float2 f0 = __half22float2(h0);
        float2 f1 = __half22float2(h1);
        const float ce = c[e];
        a0 += ce * f0.x; a1 += ce * f0.y; a2 += ce * f1.x; a3 += ce * f1.y;
    }
    *reinterpret_cast<float4*>(out + (size_t)b * U_SZ + u0) = make_float4(a0, a1, a2, a3);
}

// ----------------------------------------------------------------------------
extern "C" void kernel_launch(void* const* d_in, const int* in_sizes, int n_in,
                              void* d_out, int out_size) {
    (void)in_sizes; (void)n_in; (void)out_size;
    const float* X    = (const float*)d_in[0];  // [B, D]
    const float* tp   = (const float*)d_in[1];  // [B, E, 1]
    const float* W    = (const float*)d_in[2];  // [E, D, U]
    const float* bias = (const float*)d_in[3];  // [E, U]
    float* out = (float*)d_out;

    cudaFuncSetAttribute(gemm_exp_kernel,
                         cudaFuncAttributeMaxDynamicSharedMemorySize, SMEM_TOTAL);

    conv_x_kernel<<<(B_SZ * D_K) / 256, 256>>>(X);
    conv_w_kernel<<<dim3(U_SZ / 32, D_K / 32, E_SZ), dim3(32, 8)>>>(W);
    gemm_exp_kernel<<<dim3(U_SZ / TN, B_SZ / TM, E_SZ), ATHREADS, SMEM_TOTAL>>>(bias);
    combine_kernel<<<B_SZ, 256>>>(tp, out);
}